// round 10
// baseline (speedup 1.0000x reference)
#include <cuda_runtime.h>
#include <cuda_bf16.h>
#include <math.h>

// Static shapes: B=2048, D=256, K = D/2-1 = 127. Output R[2048,256,256] fp32.
// Nonzeros (even rows r only):
//   col r-2 -> sin(p*theta_{(r-2)/2})    (r >= 2)
//   col r   -> cos(p*theta_{min(r/2,126)})
//   col r+2 -> -sin(p*theta_{r/2})       (r/2 <= 126)
// theta_i = 10000^(-2*(i-1)/256)
//
// Grid: 8192 blocks = 2048 matrices x 4 chunks (R5 structure). R10 changes:
//  - Phase-1 zeros use 256-bit st.global.v8.b32 (8 per thread instead of 16
//    128-bit stores), with L2 eviction hints:
//      p <  RESIDENT_P : evict_last  (108 MB pinned across graph replays)
//      p >= RESIDENT_P : evict_first (stream; doesn't thrash the pinned set)
//  - Patches are plain float4 stores after __syncthreads(); phase-1 zero of
//    any patched quad is by a thread of the SAME block, so sync orders it.

#define K_ITERS 127
#define RESIDENT_P 432   // 432 matrices * 256KB = 108 MB (< 126 MB L2)

__device__ __forceinline__ void stz8_last(void* a) {
    asm volatile("st.global.L2::evict_last.v8.b32 [%0], {%1,%1,%1,%1,%1,%1,%1,%1};"
                 :: "l"(a), "r"(0u) : "memory");
}
__device__ __forceinline__ void stz8_first(void* a) {
    asm volatile("st.global.L2::evict_first.v8.b32 [%0], {%1,%1,%1,%1,%1,%1,%1,%1};"
                 :: "l"(a), "r"(0u) : "memory");
}

__global__ __launch_bounds__(256) void rope_kernel(float4* __restrict__ out) {
    // Table slice: indices i = off + t, t in [0,36), off = 2*k0 - 1.
    __shared__ float s_c[36];
    __shared__ float s_s[36];

    const int tid = threadIdx.x;
    const int p   = blockIdx.x >> 2;
    const int q   = blockIdx.x & 3;
    const int k0  = q << 4;              // first row-group of this chunk
    const int off = 2 * k0 - 1;

    // Phase 1a: table slice (2 warps of heavy math; overlaps with zeros below).
    if (tid < 36) {
        const int i = off + tid;
        if (i >= 0 && i < K_ITERS) {
            const double e = -2.0 * ((double)i - 1.0) / 256.0;
            const float theta = (float)exp(e * 9.210340371976184);  // ln(10000)
            const float m = (float)p * theta;
            s_s[tid] = sinf(m);
            s_c[tid] = cosf(m);
        }
    }

    // Phase 1b: stream zeros for this chunk with 32B stores.
    // Chunk = 4096 quads = 2048 octs (32B units). Thread tid owns octs
    // tid + 256*k, k = 0..7  ->  quad offset 2*tid + 512*k.
    float4* cbase = out + ((size_t)p << 14) + ((size_t)k0 << 8);  // chunk base
    float4* obase = cbase + 2 * tid;
    if (p < RESIDENT_P) {
#pragma unroll
        for (int k = 0; k < 8; k++) stz8_last(obase + (k << 9));
    } else {
#pragma unroll
        for (int k = 0; k < 8; k++) stz8_first(obase + (k << 9));
    }

    __syncthreads();

    // Phase 2: patches (plain 128-bit stores; ordered after the block's zeros
    // by the sync; each chunk's quads are written only by its own block).
#define SSx(i) s_s[(i) - off]
#define SCx(i) s_c[(i) - off]
    float4* mbase = out + ((size_t)p << 14) + tid;        // matrix base + tid
    const int h = tid >> 6;
    const int j = tid & 63;
    const int k1 = k0 + 16;
    if (h == 0) {
        // row 4j, quad j: .x = cos_{2j}, .z = -sin_{2j}
        if (j >= k0 && j < k1)
            mbase[j << 8] = make_float4(SCx(2 * j), 0.f, -SSx(2 * j), 0.f);
        // row 4j+4, quad j: .z = sin_{2j+1}
        if (j <= 62 && (j + 1) >= k0 && (j + 1) < k1)
            mbase[(j + 1) << 8] = make_float4(0.f, 0.f, SSx(2 * j + 1), 0.f);
    } else if (h == 2) {
        // row 4j+2, quad j: .x = sin_{2j}, .z = cos_{min(2j+1,126)}
        if (j >= k0 && j < k1) {
            int i = 2 * j + 1; if (i > K_ITERS - 1) i = K_ITERS - 1;
            mbase[j << 8] = make_float4(SSx(2 * j), 0.f, SCx(i), 0.f);
        }
        // row 4j-2, quad j: .x = -sin_{2j-1}
        if (j >= 1 && (j - 1) >= k0 && (j - 1) < k1)
            mbase[(j - 1) << 8] = make_float4(-SSx(2 * j - 1), 0.f, 0.f, 0.f);
    }
#undef SSx
#undef SCx
}

extern "C" void kernel_launch(void* const* d_in, const int* in_sizes, int n_in,
                              void* d_out, int out_size) {
    (void)d_in; (void)in_sizes; (void)n_in; (void)out_size;
    rope_kernel<<<8192, 256, 0, 0>>>((float4*)d_out);
}

// round 11
// speedup vs baseline: 1.2001x; 1.2001x over previous
#include <cuda_runtime.h>
#include <cuda_bf16.h>
#include <math.h>

// Static shapes: B=2048, D=256, K = D/2-1 = 127. Output R[2048,256,256] fp32.
// Nonzeros (even rows r only):
//   col r-2 -> sin(p*theta_{(r-2)/2})    (r >= 2)
//   col r   -> cos(p*theta_{min(r/2,126)})
//   col r+2 -> -sin(p*theta_{r/2})       (r/2 <= 126)
// theta_i = 10000^(-2*(i-1)/256)
//
// Grid: 8192 blocks = 2048 matrices x 4 chunks (R5 structure, best measured).
// R11 = controlled A/B vs R5: phase-1 zeros use plain 256-bit st.global.v8.b32
// (8 stores/thread instead of 16 STG.128), NO eviction hints (R10 showed the
// hints cause the regression). Everything else identical to R5.

#define K_ITERS 127

__device__ __forceinline__ void stz8(void* a) {
    asm volatile("st.global.v8.b32 [%0], {%1,%1,%1,%1,%1,%1,%1,%1};"
                 :: "l"(a), "r"(0u) : "memory");
}

__global__ __launch_bounds__(256) void rope_kernel(float4* __restrict__ out) {
    // Table slice: indices i = off + t, t in [0,36), off = 2*k0 - 1.
    __shared__ float s_c[36];
    __shared__ float s_s[36];

    const int tid = threadIdx.x;
    const int p   = blockIdx.x >> 2;
    const int q   = blockIdx.x & 3;
    const int k0  = q << 4;              // first row-group of this chunk
    const int off = 2 * k0 - 1;

    // Phase 1a: table slice (2 warps of heavy math; overlaps with zeros below).
    if (tid < 36) {
        const int i = off + tid;
        if (i >= 0 && i < K_ITERS) {
            const double e = -2.0 * ((double)i - 1.0) / 256.0;
            const float theta = (float)exp(e * 9.210340371976184);  // ln(10000)
            const float m = (float)p * theta;
            s_s[tid] = sinf(m);
            s_c[tid] = cosf(m);
        }
    }

    // Phase 1b: stream zeros for this chunk with 32B stores.
    // Chunk = 4096 quads = 2048 octs (32B units). Thread tid owns octs
    // tid + 256*k, k = 0..7  ->  quad offset 2*tid + 512*k.
    float4* cbase = out + ((size_t)p << 14) + ((size_t)k0 << 8);  // chunk base
    float4* obase = cbase + 2 * tid;
#pragma unroll
    for (int k = 0; k < 8; k++) stz8(obase + (k << 9));

    __syncthreads();

    // Phase 2: patches (plain 128-bit stores; ordered after this block's
    // zeros by the sync; each chunk is written only by its own block).
#define SSx(i) s_s[(i) - off]
#define SCx(i) s_c[(i) - off]
    float4* mbase = out + ((size_t)p << 14) + tid;        // matrix base + tid
    const int h = tid >> 6;
    const int j = tid & 63;
    const int k1 = k0 + 16;
    if (h == 0) {
        // row 4j, quad j: .x = cos_{2j}, .z = -sin_{2j}
        if (j >= k0 && j < k1)
            mbase[j << 8] = make_float4(SCx(2 * j), 0.f, -SSx(2 * j), 0.f);
        // row 4j+4, quad j: .z = sin_{2j+1}
        if (j <= 62 && (j + 1) >= k0 && (j + 1) < k1)
            mbase[(j + 1) << 8] = make_float4(0.f, 0.f, SSx(2 * j + 1), 0.f);
    } else if (h == 2) {
        // row 4j+2, quad j: .x = sin_{2j}, .z = cos_{min(2j+1,126)}
        if (j >= k0 && j < k1) {
            int i = 2 * j + 1; if (i > K_ITERS - 1) i = K_ITERS - 1;
            mbase[j << 8] = make_float4(SSx(2 * j), 0.f, SCx(i), 0.f);
        }
        // row 4j-2, quad j: .x = -sin_{2j-1}
        if (j >= 1 && (j - 1) >= k0 && (j - 1) < k1)
            mbase[(j - 1) << 8] = make_float4(-SSx(2 * j - 1), 0.f, 0.f, 0.f);
    }
#undef SSx
#undef SCx
}

extern "C" void kernel_launch(void* const* d_in, const int* in_sizes, int n_in,
                              void* d_out, int out_size) {
    (void)d_in; (void)in_sizes; (void)n_in; (void)out_size;
    rope_kernel<<<8192, 256, 0, 0>>>((float4*)d_out);
}

// round 12
// speedup vs baseline: 1.2072x; 1.0059x over previous
#include <cuda_runtime.h>
#include <cuda_bf16.h>
#include <math.h>

// FINAL — best measured configuration (R5; reproduced R8).
//
// Static shapes: B=2048, D=256, K = D/2-1 = 127. Output R[2048,256,256] fp32
// (512 MiB, ~0.6% nonzero). Pure HBM-write-bound: kernel streams the full
// output at ~6.5 TB/s (81% of spec, matching the CE-memset ceiling) while
// placing the nonzeros inline.
//
// Nonzeros (even rows r only):
//   col r-2 -> sin(p*theta_{(r-2)/2})    (r >= 2)
//   col r   -> cos(p*theta_{min(r/2,126)})
//   col r+2 -> -sin(p*theta_{r/2})       (r/2 <= 126)
// theta_i = 10000^(-2*(i-1)/256), theta computed in double then fp32 so the
// fp32 phase p*theta matches the reference to ~1 ulp (rel_err 2.9e-8).
//
// Grid: 8192 blocks = 2048 matrices x 4 chunks. Chunk q owns row-groups
// kp in [16q, 16q+16) (group = 4 rows = 256 quads). Thread tid = h*64+j
// writes quad (kp*256 + tid) for each kp: 16 warp-uniform STG.128 of zeros
// (table build on 36 lanes overlaps underneath), then <=2 patch STG.128
// overwriting the near-diagonal quads (same thread, same address -> program
// order, patch wins).
//
// Tested and rejected: eviction hints (regress), skip-patch predication
// (fragments warp stores, -40%), v8.b32 width (neutral), fused-per-element
// (10x regress), memset+scatter (serialized 18.8us tail).

#define K_ITERS 127

__global__ __launch_bounds__(256) void rope_kernel(float4* __restrict__ out) {
    // Table slice: indices i = off + t, t in [0,36), off = 2*k0 - 1.
    __shared__ float s_c[36];
    __shared__ float s_s[36];

    const int tid = threadIdx.x;
    const int p   = blockIdx.x >> 2;
    const int q   = blockIdx.x & 3;
    const int k0  = q << 4;              // first row-group of this chunk
    const int off = 2 * k0 - 1;

    // Phase 1a: table slice (2 warps of heavy math; overlaps with zeros below).
    if (tid < 36) {
        const int i = off + tid;
        if (i >= 0 && i < K_ITERS) {
            const double e = -2.0 * ((double)i - 1.0) / 256.0;
            const float theta = (float)exp(e * 9.210340371976184);  // ln(10000)
            const float m = (float)p * theta;
            s_s[tid] = sinf(m);
            s_c[tid] = cosf(m);
        }
    }

    // Phase 1b: stream zeros for this chunk (no dependence on the table).
    float4* mbase = out + ((size_t)p << 14) + tid;        // matrix base + tid
    float4* zbase = mbase + ((size_t)k0 << 8);            // chunk base
    const float4 z = make_float4(0.f, 0.f, 0.f, 0.f);
#pragma unroll
    for (int k = 0; k < 16; k++) {
        __stcs(&zbase[k << 8], z);       // STG.E.128.CS [R + k*4096], zeros
    }

    __syncthreads();

    // Phase 2: patches. SSx/SCx index the slice.
#define SSx(i) s_s[(i) - off]
#define SCx(i) s_c[(i) - off]
    const int h = tid >> 6;
    const int j = tid & 63;
    const int k1 = k0 + 16;
    if (h == 0) {
        // row 4j, quad j: .x = cos_{2j}, .z = -sin_{2j}
        if (j >= k0 && j < k1)
            mbase[j << 8] = make_float4(SCx(2 * j), 0.f, -SSx(2 * j), 0.f);
        // row 4j+4, quad j: .z = sin_{2j+1}
        if (j <= 62 && (j + 1) >= k0 && (j + 1) < k1)
            mbase[(j + 1) << 8] = make_float4(0.f, 0.f, SSx(2 * j + 1), 0.f);
    } else if (h == 2) {
        // row 4j+2, quad j: .x = sin_{2j}, .z = cos_{min(2j+1,126)}
        if (j >= k0 && j < k1) {
            int i = 2 * j + 1; if (i > K_ITERS - 1) i = K_ITERS - 1;
            mbase[j << 8] = make_float4(SSx(2 * j), 0.f, SCx(i), 0.f);
        }
        // row 4j-2, quad j: .x = -sin_{2j-1}
        if (j >= 1 && (j - 1) >= k0 && (j - 1) < k1)
            mbase[(j - 1) << 8] = make_float4(-SSx(2 * j - 1), 0.f, 0.f, 0.f);
    }
#undef SSx
#undef SCx
}

extern "C" void kernel_launch(void* const* d_in, const int* in_sizes, int n_in,
                              void* d_out, int out_size) {
    (void)d_in; (void)in_sizes; (void)n_in; (void)out_size;
    rope_kernel<<<8192, 256, 0, 0>>>((float4*)d_out);
}